// round 17
// baseline (speedup 1.0000x reference)
#include <cuda_runtime.h>
#include <cuda_fp16.h>
#include <cstdint>

// BG_LSTM R17: fp16 1-term HMMA + DSMEM gather exchange.
// R14 base (proven 1687us): 16 clusters x 16 CTAs (non-portable), 128
// threads/CTA. Cluster owns 32 batches; CTA rank owns 16 units (64 gate
// rows). W_hh: one fp16 SMEM plane.
// R17 delta: h exchange via DSMEM instead of global/L2. Each CTA writes
// its h slice to a double-buffered 1KB stage in its OWN SMEM (plain STS);
// after the (unchanged) release/acquire cluster barrier, each CTA gathers
// all peers' stages with ld.shared::cluster into its B plane. No
// mbarriers, no st.async, no global h buffer.
// FC head from fp32 register h via global partials.

#define TT 512
#define RANKS 16
#define NT 128
#define MROWS 64
#define ASTR 264            // fp16 elems per plane row (528 B)

// FC partials: [tile][rank][batch]
__device__ float g_fcpart[16][16][32];

extern __shared__ __align__(16) char smem_raw[];

// ---- SMEM offsets (from 1KB-aligned base) ----
#define OFF_B   33792u      // W plane: 64*528 = 33792; B plane: 32*528
#define OFF_GS  50688u      // 4 warps x 2560 = 10240
#define OFF_XS  60928u      // 16 steps x 32 b fp32 = 2048
#define OFF_STG 62976u      // 2 x 1KB h stage [b][u_local] fp16
#define SM_BYTES (65024 + 1024)

// ---------------- asm helpers ----------------
static __device__ __forceinline__ uint32_t smem_u32(const void* p) {
    uint32_t a;
    asm("{ .reg .u64 t; cvta.to.shared.u64 t, %1; cvt.u32.u64 %0, t; }"
        : "=r"(a) : "l"(p));
    return a;
}
static __device__ __forceinline__ void sts16(uint32_t a, uint16_t v) {
    asm volatile("st.shared.u16 [%0], %1;" :: "r"(a), "h"(v));
}
static __device__ __forceinline__ void sts128(uint32_t a, uint4 v) {
    asm volatile("st.shared.v4.b32 [%0], {%1,%2,%3,%4};"
                 :: "r"(a), "r"(v.x), "r"(v.y), "r"(v.z), "r"(v.w));
}
static __device__ __forceinline__ void sts32f(uint32_t a, float v) {
    asm volatile("st.shared.f32 [%0], %1;" :: "r"(a), "f"(v));
}
static __device__ __forceinline__ void sts32u(uint32_t a, uint32_t v) {
    asm volatile("st.shared.b32 [%0], %1;" :: "r"(a), "r"(v));
}
static __device__ __forceinline__ float lds32f(uint32_t a) {
    float v; asm volatile("ld.shared.f32 %0, [%1];" : "=f"(v) : "r"(a));
    return v;
}
static __device__ __forceinline__ float4 lds128f(uint32_t a) {
    float4 v;
    asm volatile("ld.shared.v4.f32 {%0,%1,%2,%3}, [%4];"
                 : "=f"(v.x), "=f"(v.y), "=f"(v.z), "=f"(v.w) : "r"(a));
    return v;
}
static __device__ __forceinline__ uint4 ldsc128(uint32_t a) {
    uint4 v;
    asm volatile("ld.shared::cluster.v4.b32 {%0,%1,%2,%3}, [%4];"
                 : "=r"(v.x), "=r"(v.y), "=r"(v.z), "=r"(v.w) : "r"(a));
    return v;
}
static __device__ __forceinline__ void ldsm4(uint32_t* r, uint32_t a) {
    asm volatile("ldmatrix.sync.aligned.m8n8.x4.shared.b16 {%0,%1,%2,%3}, [%4];"
                 : "=r"(r[0]), "=r"(r[1]), "=r"(r[2]), "=r"(r[3]) : "r"(a));
}
static __device__ __forceinline__ void mma16816(float* c, const uint32_t* a,
                                                const uint32_t* b) {
    asm volatile(
        "mma.sync.aligned.m16n8k16.row.col.f32.f16.f16.f32 "
        "{%0,%1,%2,%3},{%4,%5,%6,%7},{%8,%9},{%0,%1,%2,%3};"
        : "+f"(c[0]), "+f"(c[1]), "+f"(c[2]), "+f"(c[3])
        : "r"(a[0]), "r"(a[1]), "r"(a[2]), "r"(a[3]), "r"(b[0]), "r"(b[1]));
}
static __device__ __forceinline__ uint32_t mapa_sh(uint32_t a, uint32_t r) {
    uint32_t d; asm("mapa.shared::cluster.u32 %0, %1, %2;" : "=r"(d) : "r"(a), "r"(r));
    return d;
}
static __device__ __forceinline__ void cluster_arrive_rel() {
    asm volatile("barrier.cluster.arrive.release.aligned;" ::: "memory");
}
static __device__ __forceinline__ void cluster_wait_acq() {
    asm volatile("barrier.cluster.wait.acquire.aligned;" ::: "memory");
}
static __device__ __forceinline__ float tanh_a(float x) {
    float y; asm("tanh.approx.f32 %0, %1;" : "=f"(y) : "f"(x)); return y;
}
static __device__ __forceinline__ float sigm(float x) {
    return fmaf(0.5f, tanh_a(0.5f * x), 0.5f);
}

__global__ void __launch_bounds__(NT, 1)
lstm_kernel(const float* __restrict__ x,    const float* __restrict__ wih,
            const float* __restrict__ whh,  const float* __restrict__ bih,
            const float* __restrict__ bhh,  const float* __restrict__ wfc,
            const float* __restrict__ bfc,  float* __restrict__ out)
{
    const int t      = threadIdx.x;
    const int lane   = t & 31;
    const int w      = t >> 5;          // warp 0..3
    const int cta    = blockIdx.x;
    const int rank   = cta % RANKS;
    const int cl     = cta / RANKS;     // tile 0..15
    const int batch0 = cl * 32;
    const int unit0  = rank * 16;

    const uint32_t base = (smem_u32(smem_raw) + 1023u) & ~1023u;
    const uint32_t sW   = base;
    const uint32_t sB   = base + OFF_B;
    const uint32_t sGS  = base + OFF_GS;
    const uint32_t sXS  = base + OFF_XS;
    const uint32_t sSTG = base + OFF_STG;

    // ---- One-time: W -> single fp16 plane. Row m = u*4+g (u local). ----
    if (t < MROWS) {
        const int m = t;
        const float* wrow = whh + ((size_t)((m & 3) * 256 + unit0 + (m >> 2))) * 256;
        uint32_t aw = sW + (uint32_t)(m * ASTR * 2);
        #pragma unroll 8
        for (int k2 = 0; k2 < 128; k2++) {
            float2 wv = *(const float2*)(wrow + 2 * k2);
            uint32_t hi = ((uint32_t)__half_as_ushort(__float2half(wv.y)) << 16) |
                          (uint32_t)__half_as_ushort(__float2half(wv.x));
            sts32u(aw + 4u * k2, hi);
        }
    }

    // ---- Zero stage buffer 0 (h(0) = 0): 1KB = 256 u32 ----
    sts32u(sSTG + 4u * (uint32_t)t, 0u);
    sts32u(sSTG + 4u * (uint32_t)(t + NT), 0u);

    // ---- Per-thread activation params: u = t>>3 (0..15), b = 4(t&7)+j ----
    const int u  = t >> 3;
    const int bq = t & 7;
    float wihr[4], biasr[4];
    #pragma unroll
    for (int g = 0; g < 4; g++) {
        int r = g * 256 + unit0 + u;
        wihr[g]  = __ldg(&wih[r]);
        biasr[g] = __ldg(&bih[r]) + __ldg(&bhh[r]);
    }
    const float wfcr = __ldg(&wfc[unit0 + u]);

    float cc[4] = {0.f, 0.f, 0.f, 0.f};
    float hv[4] = {0.f, 0.f, 0.f, 0.f};

    // ---- Peer stage base addresses (gather sources) ----
    uint32_t peerStg[RANKS];
    #pragma unroll
    for (int r = 0; r < RANKS; r++) peerStg[r] = mapa_sh(sSTG, (uint32_t)r);

    // ---- ldmatrix lane base addresses (R8 layout) ----
    const uint32_t aOff =
        (uint32_t)(((16 * w + (lane & 15)) * ASTR + ((lane >> 4) * 8)) * 2);
    uint32_t bOff[2];
    #pragma unroll
    for (int P = 0; P < 2; P++) {
        int nB = 16 * P + (lane & 7) + (((lane >> 4) & 1) << 3);
        int ka = (lane & 8) ? 8 : 0;
        bOff[P] = (uint32_t)((nB * ASTR + ka) * 2);
    }

    __syncthreads();
    cluster_arrive_rel();    // stage0 zeros + W visible cluster-wide
    cluster_wait_acq();

    for (int step = 0; step < TT; step++) {
        const uint32_t rdOff = (uint32_t)((step & 1) * 1024);

        // ---- Gather peers' h stages (DSMEM) -> B plane [b][u] ----
        #pragma unroll
        for (int i = 0; i < 8; i++) {
            int id  = t + i * NT;        // 1024 granules of 16B
            int b   = id >> 5;
            int col = id & 31;           // units col*8 .. col*8+7
            uint32_t src = peerStg[col >> 1] + rdOff
                         + (uint32_t)(b * 32 + (col & 1) * 16);
            uint4 v = ldsc128(src);
            sts128(sB + (uint32_t)(b * 528 + col * 16), v);
        }
        // ---- Stage x chunk every 16 steps: xs[(s&15)*32 + b] ----
        if ((step & 15) == 0) {
            int bx = t >> 2, i4 = t & 3;
            float4 v = __ldg((const float4*)&x[(size_t)(batch0 + bx) * TT + step] + i4);
            uint32_t a0 = sXS + (uint32_t)(((i4 * 4 + 0) * 32 + bx) * 4);
            sts32f(a0,        v.x);
            sts32f(a0 + 128u, v.y);
            sts32f(a0 + 256u, v.z);
            sts32f(a0 + 384u, v.w);
        }
        __syncthreads();

        // ---- MMA: single term W*h, 16 k-tiles ----
        float c0[4] = {0,0,0,0}, c1[4] = {0,0,0,0};
        float c2[4] = {0,0,0,0}, c3[4] = {0,0,0,0};
        uint32_t aW = sW + aOff;
        uint32_t b0 = sB + bOff[0], b1 = sB + bOff[1];
        #pragma unroll 8
        for (int kt = 0; kt < 16; kt++) {
            uint32_t ah[4], bb[8];
            ldsm4(ah, aW);
            ldsm4(bb, b0);   ldsm4(bb + 4, b1);
            aW += 32; b0 += 32; b1 += 32;
            mma16816(c0, ah, bb);      mma16816(c1, ah, bb + 2);
            mma16816(c2, ah, bb + 4);  mma16816(c3, ah, bb + 6);
        }

        // ---- D fragments -> warp-private gates scratch ----
        {
            uint32_t gw = sGS + (uint32_t)(w * 2560);
            int mr = lane >> 2;            // m_local rows mr, mr+8
            int j0 = 2 * (lane & 3);
            float* cs[4] = {c0, c1, c2, c3};
            #pragma unroll
            for (int nt = 0; nt < 4; nt++) {
                int col = nt * 8 + j0;
                sts32f(gw + (uint32_t)((col    ) * 80 + mr * 4),       cs[nt][0]);
                sts32f(gw + (uint32_t)((col + 1) * 80 + mr * 4),       cs[nt][1]);
                sts32f(gw + (uint32_t)((col    ) * 80 + (mr + 8) * 4), cs[nt][2]);
                sts32f(gw + (uint32_t)((col + 1) * 80 + (mr + 8) * 4), cs[nt][3]);
            }
        }
        __syncwarp();

        // ---- Activations: 4 cells (u, 4bq+j); write h into stage p^1 ----
        {
            uint32_t gw = sGS + (uint32_t)(w * 2560) + (uint32_t)((lane >> 3) * 16);
            uint32_t wrOff = (uint32_t)(((step + 1) & 1) * 1024);
            #pragma unroll
            for (int j = 0; j < 4; j++) {
                int b = 4 * bq + j;
                float4 gv = lds128f(gw + (uint32_t)(b * 80));
                float xv  = lds32f(sXS + (uint32_t)(((step & 15) * 32 + b) * 4));
                float gi = gv.x + fmaf(xv, wihr[0], biasr[0]);
                float gf = gv.y + fmaf(xv, wihr[1], biasr[1]);
                float gg = gv.z + fmaf(xv, wihr[2], biasr[2]);
                float go = gv.w + fmaf(xv, wihr[3], biasr[3]);
                float c = sigm(gf) * cc[j] + sigm(gi) * tanh_a(gg);
                cc[j] = c;
                hv[j] = sigm(go) * tanh_a(c);
                sts16(sSTG + wrOff + (uint32_t)(b * 32 + u * 2),
                      __half_as_ushort(__float2half(hv[j])));
            }
        }

        cluster_arrive_rel();   // release: my h(step+1) stage visible
        cluster_wait_acq();     // acquire: all peers' stages ready
    }

    // ---- FC head from fp32 register h ----
    __syncthreads();
    #pragma unroll
    for (int j = 0; j < 4; j++) {
        int b = 4 * bq + j;
        sts32f(sGS + (uint32_t)((b * 16 + u) * 4), fmaxf(hv[j], 0.f) * wfcr);
    }
    __syncthreads();
    if (t < 32) {
        float s = 0.f;
        #pragma unroll
        for (int uu = 0; uu < 16; uu++)
            s += lds32f(sGS + (uint32_t)((t * 16 + uu) * 4));
        g_fcpart[cl][rank][t] = s;
    }
    cluster_arrive_rel();    // release partials cluster-wide
    cluster_wait_acq();
    if (rank == 0 && t < 32) {
        float tot = __ldg(bfc);
        #pragma unroll
        for (int r = 0; r < RANKS; r++)
            tot += g_fcpart[cl][r][t];
        out[batch0 + t] = tot;
    }
    // keep SMEM alive until the whole cluster is done
    cluster_arrive_rel();
    cluster_wait_acq();
}

extern "C" void kernel_launch(void* const* d_in, const int* in_sizes, int n_in,
                              void* d_out, int out_size) {
    const float* x   = (const float*)d_in[0];
    const float* wih = (const float*)d_in[1];
    const float* whh = (const float*)d_in[2];
    const float* bih = (const float*)d_in[3];
    const float* bhh = (const float*)d_in[4];
    const float* wfc = (const float*)d_in[5];
    const float* bfc = (const float*)d_in[6];
    (void)in_sizes; (void)n_in; (void)out_size;

    cudaFuncSetAttribute(lstm_kernel,
                         cudaFuncAttributeMaxDynamicSharedMemorySize, SM_BYTES);
    cudaFuncSetAttribute(lstm_kernel,
                         cudaFuncAttributeNonPortableClusterSizeAllowed, 1);

    cudaLaunchConfig_t cfg = {};
    cfg.gridDim  = {256, 1, 1};
    cfg.blockDim = {NT, 1, 1};
    cfg.dynamicSmemBytes = SM_BYTES;
    cudaLaunchAttribute at[1];
    at[0].id = cudaLaunchAttributeClusterDimension;
    at[0].val.clusterDim = {RANKS, 1, 1};
    cfg.attrs = at; cfg.numAttrs = 1;
    cudaLaunchKernelEx(&cfg, lstm_kernel, x, wih, whh, bih, bhh, wfc, bfc,
                       (float*)d_out);
}